// round 13
// baseline (speedup 1.0000x reference)
#include <cuda_runtime.h>
#include <cuda_bf16.h>
#include <cstdint>

#define DD    32
#define KK    128          // 4 groups of 32: A=(q,ph,ph,pl) * B=(w',ah,al,ah); q*wbar exact in epilogue
#define KPAD  136          // bf16 per smem row: 272B stride -> ldmatrix conflict-free
#define NROW  16           // int4 chunks per 128-bf16 row
#define TNPTS 64           // n-strip rows per block (2 blocks/SM)
#define TMC   128
#define NMAX  16384
#define MMAX  1024
#define NTILE (MMAX / TMC) // 8 m-tiles per block

__device__ __nv_bfloat16 g_A[NMAX * KK];  // [n][k]
__device__ __nv_bfloat16 g_B[MMAX * KK];  // [m][k]
__device__ float g_eb[MMAX];              // CEXP*sum(c^2/s^2) + log2(1/detS)
__device__ float g_rc[NMAX];              // exact fp32: sum_d q_d * wbar_d

// ---------------- helpers ----------------
__device__ __forceinline__ uint32_t smem_u32(const void* p) {
    uint32_t a;
    asm("{ .reg .u64 t; cvta.to.shared.u64 t, %1; cvt.u32.u64 %0, t; }" : "=r"(a) : "l"(p));
    return a;
}
__device__ __forceinline__ float ex2(float v) {
    float r; asm("ex2.approx.ftz.f32 %0, %1;" : "=f"(r) : "f"(v)); return r;
}
__device__ __forceinline__ void cp16(uint32_t smem_addr, const void* gptr) {
    asm volatile("cp.async.cg.shared.global [%0], [%1], 16;" :: "r"(smem_addr), "l"(gptr));
}
__device__ __forceinline__ void ldsm_x4(uint32_t& r0, uint32_t& r1, uint32_t& r2, uint32_t& r3,
                                        uint32_t addr) {
    asm volatile("ldmatrix.sync.aligned.m8n8.x4.shared.b16 {%0,%1,%2,%3}, [%4];"
                 : "=r"(r0), "=r"(r1), "=r"(r2), "=r"(r3) : "r"(addr));
}
__device__ __forceinline__ void mma_bf16(float* c, const uint32_t* a, uint32_t b0, uint32_t b1) {
    asm volatile(
        "mma.sync.aligned.m16n8k16.row.col.f32.bf16.bf16.f32 "
        "{%0,%1,%2,%3}, {%4,%5,%6,%7}, {%8,%9}, {%0,%1,%2,%3};"
        : "+f"(c[0]), "+f"(c[1]), "+f"(c[2]), "+f"(c[3])
        : "r"(a[0]), "r"(a[1]), "r"(a[2]), "r"(a[3]), "r"(b0), "r"(b1));
}
__device__ __forceinline__ __nv_bfloat16 bfh(float v) { return __float2bfloat16_rn(v); }

// ---------------- fused precompute: one lane per (row, d); warp = one row ----------------
__global__ __launch_bounds__(256) void rbf_precompute(const float* __restrict__ x,
                                                      const float* __restrict__ centers,
                                                      const float* __restrict__ sigma,
                                                      int N, int M) {
    int idx = blockIdx.x * 256 + threadIdx.x;   // idx = row*32 + d
    int d = idx & 31;
    const float CEXP = -0.7213475204444817f;    // -0.5 * log2(e)
    const float LOG2_2PI = 2.6514961294723187f;

    float s0  = sigma[d];
    float wbar = CEXP * __frcp_rn(s0 * s0);

    // --- A side: groups [q, ph, ph, pl]; rc = sum q*wbar exact ---
    {
        int n = idx >> 5;
        float v = x[idx];
        __nv_bfloat16 ph = bfh(v);
        __nv_bfloat16 pl = bfh(v - __bfloat162float(ph));
        float q = v * v;
        __nv_bfloat16 qb = bfh(q);
        __nv_bfloat16* row = g_A + (size_t)n * KK + d;
        row[0 * 32] = qb;  row[1 * 32] = ph;  row[2 * 32] = ph;  row[3 * 32] = pl;

        float rc = q * wbar;
#pragma unroll
        for (int o = 16; o > 0; o >>= 1)
            rc += __shfl_xor_sync(0xFFFFFFFFu, rc, o);
        if (d == 0) g_rc[n] = rc;
    }

    // --- B side: groups [w', ah, al, ah] ---
    if (idx < M * DD) {
        int m = idx >> 5;
        float c  = centers[idx];
        float s  = sigma[idx];
        float s2 = s * s;
        float inv = __frcp_rn(s2);
        float w  = CEXP * inv;
        float wp = w - wbar;                       // residual (0 when sigma uniform)
        float a  = -2.0f * c * w;
        __nv_bfloat16 wpb = bfh(wp);
        __nv_bfloat16 ah = bfh(a);
        __nv_bfloat16 al = bfh(a - __bfloat162float(ah));
        __nv_bfloat16* row = g_B + (size_t)m * KK + d;
        row[0 * 32] = wpb;  row[1 * 32] = ah;  row[2 * 32] = al;  row[3 * 32] = ah;

        float cm = c * c * inv;
        float lg = __log2f(s2);
#pragma unroll
        for (int o = 16; o > 0; o >>= 1) {
            cm += __shfl_xor_sync(0xFFFFFFFFu, cm, o);
            lg += __shfl_xor_sync(0xFFFFFFFFu, lg, o);
        }
        if (d == 0)
            g_eb[m] = fmaf(CEXP, cm, -0.5f * (DD * LOG2_2PI + lg));
    }
}

// ---- 64-row strip GEMM (K=128), 2 blocks/SM, B double-buffered ----
__global__ __launch_bounds__(256, 2)
void rbf_gemm(float* __restrict__ out, int N, int M) {
    extern __shared__ char dyn[];
    __nv_bfloat16* a_s  = (__nv_bfloat16*)dyn;             // [64][KPAD]     17 KB
    __nv_bfloat16* b_s  = a_s + TNPTS * KPAD;              // [2][128][KPAD] 70 KB
    float*         eb_s = (float*)(b_s + 2 * TMC * KPAD);  // [1024]          4 KB
    float*         rc_s = eb_s + MMAX;                     // [64]

    const int tid  = threadIdx.x;
    const int wid  = tid >> 5;
    const int lane = tid & 31;
    const int n0 = blockIdx.x * TNPTS;

    const uint32_t a_u = smem_u32(a_s);
    const uint32_t b_u = smem_u32(b_s);
    const uint32_t bufstride = (uint32_t)(TMC * KPAD * 2);

    // --- Prologue: A tile + B tile 0 + eb + rc ---
    for (int i = tid; i < TNPTS * NROW; i += 256) {
        int r = i >> 4, c = i & 15;
        cp16(a_u + (uint32_t)(r * (KPAD * 2) + c * 16),
             (const char*)(g_A + (size_t)(n0 + r) * KK) + c * 16);
    }
    for (int i = tid; i < TMC * NROW; i += 256) {
        int r = i >> 4, c = i & 15;
        cp16(b_u + (uint32_t)(r * (KPAD * 2) + c * 16),
             (const char*)(g_B + (size_t)r * KK) + c * 16);
    }
    asm volatile("cp.async.commit_group;" ::: "memory");
    *(float4*)(eb_s + tid * 4) = *(const float4*)(g_eb + tid * 4);
    if (tid < TNPTS) rc_s[tid] = g_rc[n0 + tid];
    asm volatile("cp.async.wait_group 0;" ::: "memory");
    __syncthreads();

    // --- Warp tiling: 2 (rows) x 4 (cols) warps; warp tile 32 x 32 ---
    const int warp_m = (wid & 1) * 32;         // n-row offset
    const int warp_n = (wid >> 1) * 32;        // m-col offset

    const uint32_t a_base = a_u + (uint32_t)(warp_m + (lane & 15)) * (KPAD * 2)
                          + ((uint32_t)lane >> 4) * 16u;
    const uint32_t b_frag = (uint32_t)((warp_n + ((lane >> 4) & 1) * 8 + (lane & 7)) * (KPAD * 2))
                          + (uint32_t)((lane >> 3) & 1) * 16u;
    const int qrow = lane >> 2;
    const int qcol = 2 * (lane & 3);

    for (int mt = 0; mt < NTILE; mt++) {
        if (mt + 1 < NTILE) {
            uint32_t dst = b_u + (uint32_t)((mt + 1) & 1) * bufstride;
            const char* src = (const char*)(g_B + (size_t)(mt + 1) * TMC * KK);
            for (int i = tid; i < TMC * NROW; i += 256) {
                int r = i >> 4, c = i & 15;
                cp16(dst + (uint32_t)(r * (KPAD * 2) + c * 16), src + (size_t)r * KK * 2 + c * 16);
            }
            asm volatile("cp.async.commit_group;" ::: "memory");
            asm volatile("cp.async.wait_group 1;" ::: "memory");
        } else {
            asm volatile("cp.async.wait_group 0;" ::: "memory");
        }
        __syncthreads();

        const uint32_t b_base = b_u + (uint32_t)(mt & 1) * bufstride + b_frag;

        float acc[2][4][4];
#pragma unroll
        for (int i = 0; i < 2; i++)
#pragma unroll
            for (int j = 0; j < 4; j++)
#pragma unroll
                for (int k = 0; k < 4; k++) acc[i][j][k] = 0.0f;

#pragma unroll
        for (int s = 0; s < KK / 16; s++) {
            uint32_t af[2][4];
#pragma unroll
            for (int mi = 0; mi < 2; mi++)
                ldsm_x4(af[mi][0], af[mi][1], af[mi][2], af[mi][3],
                        a_base + (uint32_t)mi * (16 * KPAD * 2) + (uint32_t)s * 32u);
            uint32_t bf[4][2];
#pragma unroll
            for (int nj2 = 0; nj2 < 2; nj2++) {
                uint32_t r0, r1, r2, r3;
                ldsm_x4(r0, r1, r2, r3,
                        b_base + (uint32_t)nj2 * (16 * KPAD * 2) + (uint32_t)s * 32u);
                bf[nj2 * 2 + 0][0] = r0; bf[nj2 * 2 + 0][1] = r1;
                bf[nj2 * 2 + 1][0] = r2; bf[nj2 * 2 + 1][1] = r3;
            }
#pragma unroll
            for (int mi = 0; mi < 2; mi++)
#pragma unroll
                for (int nt = 0; nt < 4; nt++)
                    mma_bf16(acc[mi][nt], af[mi], bf[nt][0], bf[nt][1]);
        }

        // --- Epilogue: out = exp2(acc + eb[m] + rc[n]) ---
        const int m0 = mt * TMC;
#pragma unroll
        for (int mi = 0; mi < 2; mi++) {
            int lrow = warp_m + mi * 16 + qrow;
            int row0 = n0 + lrow;
            float rc0 = rc_s[lrow];
            float rc1 = rc_s[lrow + 8];
#pragma unroll
            for (int nt = 0; nt < 4; nt++) {
                int col_l = warp_n + nt * 8 + qcol;
                float2 ebv = *(const float2*)(eb_s + m0 + col_l);
                float* p0 = out + (size_t)row0 * M + m0 + col_l;
                float2 r0, r1;
                r0.x = ex2(acc[mi][nt][0] + ebv.x + rc0);
                r0.y = ex2(acc[mi][nt][1] + ebv.y + rc0);
                r1.x = ex2(acc[mi][nt][2] + ebv.x + rc1);
                r1.y = ex2(acc[mi][nt][3] + ebv.y + rc1);
                *(float2*)(p0) = r0;
                *(float2*)(p0 + (size_t)8 * M) = r1;
            }
        }
        __syncthreads();
    }
}

extern "C" void kernel_launch(void* const* d_in, const int* in_sizes, int n_in,
                              void* d_out, int out_size) {
    const float* x       = (const float*)d_in[0];
    const float* centers = (const float*)d_in[1];
    const float* sigma   = (const float*)d_in[2];
    float* out = (float*)d_out;

    int N = in_sizes[0] / DD;
    int M = in_sizes[1] / DD;

    rbf_precompute<<<(N * DD) / 256, 256>>>(x, centers, sigma, N, M);

    const int SMEM_BYTES = TNPTS * KPAD * 2 + 2 * TMC * KPAD * 2 + MMAX * 4 + TNPTS * 4; // ~91 KB
    cudaFuncSetAttribute(rbf_gemm, cudaFuncAttributeMaxDynamicSharedMemorySize, SMEM_BYTES);

    rbf_gemm<<<N / TNPTS, 256, SMEM_BYTES>>>(out, N, M);
}

// round 14
// speedup vs baseline: 1.0550x; 1.0550x over previous
#include <cuda_runtime.h>
#include <cuda_bf16.h>
#include <cstdint>

#define DD    32
#define KK    128          // groups: A=(ph,ph,pl,q) * B=(ah,al,ah,w'); group 3 skipped when w'==0
#define KPAD  136          // bf16 per smem row: 272B stride -> ldmatrix conflict-free
#define NROW  16           // int4 chunks per 128-bf16 row
#define TNPTS 128
#define TMC   128
#define NMAX  16384
#define MMAX  1024
#define NTILE (MMAX / TMC)

__device__ __nv_bfloat16 g_A[NMAX * KK];
__device__ __nv_bfloat16 g_B[MMAX * KK];
__device__ float g_eb[MMAX];   // CEXP*sum(c^2/s^2) + log2(1/detS)
__device__ float g_rc[NMAX];   // exact fp32: sum_d q_d * wbar_d
__device__ int   g_flag;       // 1 if any w' != 0 (non-uniform sigma across centers)

// ---------------- helpers ----------------
__device__ __forceinline__ uint32_t smem_u32(const void* p) {
    uint32_t a;
    asm("{ .reg .u64 t; cvta.to.shared.u64 t, %1; cvt.u32.u64 %0, t; }" : "=r"(a) : "l"(p));
    return a;
}
__device__ __forceinline__ float ex2(float v) {
    float r; asm("ex2.approx.ftz.f32 %0, %1;" : "=f"(r) : "f"(v)); return r;
}
__device__ __forceinline__ void cp16(uint32_t smem_addr, const void* gptr) {
    asm volatile("cp.async.cg.shared.global [%0], [%1], 16;" :: "r"(smem_addr), "l"(gptr));
}
__device__ __forceinline__ void ldsm_x4(uint32_t& r0, uint32_t& r1, uint32_t& r2, uint32_t& r3,
                                        uint32_t addr) {
    asm volatile("ldmatrix.sync.aligned.m8n8.x4.shared.b16 {%0,%1,%2,%3}, [%4];"
                 : "=r"(r0), "=r"(r1), "=r"(r2), "=r"(r3) : "r"(addr));
}
__device__ __forceinline__ void mma_bf16(float* c, const uint32_t* a, uint32_t b0, uint32_t b1) {
    asm volatile(
        "mma.sync.aligned.m16n8k16.row.col.f32.bf16.bf16.f32 "
        "{%0,%1,%2,%3}, {%4,%5,%6,%7}, {%8,%9}, {%0,%1,%2,%3};"
        : "+f"(c[0]), "+f"(c[1]), "+f"(c[2]), "+f"(c[3])
        : "r"(a[0]), "r"(a[1]), "r"(a[2]), "r"(a[3]), "r"(b0), "r"(b1));
}
__device__ __forceinline__ __nv_bfloat16 bfh(float v) { return __float2bfloat16_rn(v); }

// ---------------- fused precompute: one lane per (row, d); warp = one row ----------------
__global__ __launch_bounds__(256) void rbf_precompute(const float* __restrict__ x,
                                                      const float* __restrict__ centers,
                                                      const float* __restrict__ sigma,
                                                      int N, int M) {
    int idx = blockIdx.x * 256 + threadIdx.x;   // idx = row*32 + d
    int d = idx & 31;
    const float CEXP = -0.7213475204444817f;    // -0.5 * log2(e)
    const float LOG2_2PI = 2.6514961294723187f;

    float s0   = sigma[d];                      // reference sigma (center row 0)
    float wbar = CEXP * __frcp_rn(s0 * s0);

    // --- A side: groups [ph, ph, pl, q]; rc = sum q*wbar exact ---
    {
        int n = idx >> 5;
        float v = x[idx];
        __nv_bfloat16 ph = bfh(v);
        __nv_bfloat16 pl = bfh(v - __bfloat162float(ph));
        float q = v * v;
        __nv_bfloat16 qb = bfh(q);
        __nv_bfloat16* row = g_A + (size_t)n * KK + d;
        row[0 * 32] = ph;  row[1 * 32] = ph;  row[2 * 32] = pl;  row[3 * 32] = qb;

        float rc = q * wbar;
#pragma unroll
        for (int o = 16; o > 0; o >>= 1)
            rc += __shfl_xor_sync(0xFFFFFFFFu, rc, o);
        if (d == 0) g_rc[n] = rc;
    }

    // --- B side: groups [ah, al, ah, w'] ---
    if (idx < M * DD) {
        int m = idx >> 5;
        float c  = centers[idx];
        float s  = sigma[idx];
        float s2 = s * s;
        float inv = __frcp_rn(s2);
        float w  = CEXP * inv;
        float wp = w - wbar;                       // residual (0 when sigma uniform)
        float a  = -2.0f * c * w;
        __nv_bfloat16 ah = bfh(a);
        __nv_bfloat16 al = bfh(a - __bfloat162float(ah));
        __nv_bfloat16 wpb = bfh(wp);
        __nv_bfloat16* row = g_B + (size_t)m * KK + d;
        row[0 * 32] = ah;  row[1 * 32] = al;  row[2 * 32] = ah;  row[3 * 32] = wpb;

        // flag: any nonzero residual anywhere -> full K=128 path
        unsigned ball = __ballot_sync(0xFFFFFFFFu, wp != 0.0f);
        if (d == 0 && ball) atomicOr(&g_flag, 1);

        float cm = c * c * inv;
        float lg = __log2f(s2);
#pragma unroll
        for (int o = 16; o > 0; o >>= 1) {
            cm += __shfl_xor_sync(0xFFFFFFFFu, cm, o);
            lg += __shfl_xor_sync(0xFFFFFFFFu, lg, o);
        }
        if (d == 0)
            g_eb[m] = fmaf(CEXP, cm, -0.5f * (DD * LOG2_2PI + lg));
    }
}

// ---- persistent n-strip GEMM, adaptive K (96 or 128), B double-buffered ----
__global__ __launch_bounds__(256, 1)
void rbf_gemm(float* __restrict__ out, int N, int M) {
    extern __shared__ char dyn[];
    __nv_bfloat16* a_s  = (__nv_bfloat16*)dyn;             // [128][KPAD]
    __nv_bfloat16* b_s  = a_s + TNPTS * KPAD;              // [2][128][KPAD]
    float*         eb_s = (float*)(b_s + 2 * TMC * KPAD);  // [1024]
    float*         rc_s = eb_s + MMAX;                     // [128]

    const int tid  = threadIdx.x;
    const int wid  = tid >> 5;
    const int lane = tid & 31;
    const int n0 = blockIdx.x * TNPTS;

    const int flag = g_flag;                    // uniform; 0 => skip group 3 (K=96)
    const int nchunk = flag ? NROW : 12;        // int4 chunks per row actually needed

    const uint32_t a_u = smem_u32(a_s);
    const uint32_t b_u = smem_u32(b_s);
    const uint32_t bufstride = (uint32_t)(TMC * KPAD * 2);

    // --- Prologue: A tile + B tile 0 + eb + rc ---
    for (int i = tid; i < TNPTS * nchunk; i += 256) {
        int r = i / nchunk, c = i - r * nchunk;
        cp16(a_u + (uint32_t)(r * (KPAD * 2) + c * 16),
             (const char*)(g_A + (size_t)(n0 + r) * KK) + c * 16);
    }
    for (int i = tid; i < TMC * nchunk; i += 256) {
        int r = i / nchunk, c = i - r * nchunk;
        cp16(b_u + (uint32_t)(r * (KPAD * 2) + c * 16),
             (const char*)(g_B + (size_t)r * KK) + c * 16);
    }
    asm volatile("cp.async.commit_group;" ::: "memory");
    *(float4*)(eb_s + tid * 4) = *(const float4*)(g_eb + tid * 4);
    if (tid < TNPTS) rc_s[tid] = g_rc[n0 + tid];
    asm volatile("cp.async.wait_group 0;" ::: "memory");
    __syncthreads();

    // --- Warp tiling: 2 (rows) x 4 (cols) warps; warp tile 64 x 32 ---
    const int warp_m = (wid & 1) * 64;
    const int warp_n = (wid >> 1) * 32;

    const uint32_t a_base = a_u + (uint32_t)(warp_m + (lane & 15)) * (KPAD * 2)
                          + ((uint32_t)lane >> 4) * 16u;
    const uint32_t b_frag = (uint32_t)((warp_n + ((lane >> 4) & 1) * 8 + (lane & 7)) * (KPAD * 2))
                          + (uint32_t)((lane >> 3) & 1) * 16u;
    const int qrow = lane >> 2;
    const int qcol = 2 * (lane & 3);

    for (int mt = 0; mt < NTILE; mt++) {
        if (mt + 1 < NTILE) {
            uint32_t dst = b_u + (uint32_t)((mt + 1) & 1) * bufstride;
            const char* src = (const char*)(g_B + (size_t)(mt + 1) * TMC * KK);
            for (int i = tid; i < TMC * nchunk; i += 256) {
                int r = i / nchunk, c = i - r * nchunk;
                cp16(dst + (uint32_t)(r * (KPAD * 2) + c * 16), src + (size_t)r * KK * 2 + c * 16);
            }
            asm volatile("cp.async.commit_group;" ::: "memory");
            asm volatile("cp.async.wait_group 1;" ::: "memory");
        } else {
            asm volatile("cp.async.wait_group 0;" ::: "memory");
        }
        __syncthreads();

        const uint32_t b_base = b_u + (uint32_t)(mt & 1) * bufstride + b_frag;

        float acc[4][4][4];
#pragma unroll
        for (int i = 0; i < 4; i++)
#pragma unroll
            for (int j = 0; j < 4; j++)
#pragma unroll
                for (int k = 0; k < 4; k++) acc[i][j][k] = 0.0f;

        // ksteps 0..5 (groups ph*ah, ph*al, pl*ah) always; 6..7 (q*w') only if flag
#pragma unroll
        for (int s = 0; s < 6; s++) {
            uint32_t af[4][4];
#pragma unroll
            for (int mi = 0; mi < 4; mi++)
                ldsm_x4(af[mi][0], af[mi][1], af[mi][2], af[mi][3],
                        a_base + (uint32_t)mi * (16 * KPAD * 2) + (uint32_t)s * 32u);
            uint32_t bf[4][2];
#pragma unroll
            for (int nj2 = 0; nj2 < 2; nj2++) {
                uint32_t r0, r1, r2, r3;
                ldsm_x4(r0, r1, r2, r3,
                        b_base + (uint32_t)nj2 * (16 * KPAD * 2) + (uint32_t)s * 32u);
                bf[nj2 * 2 + 0][0] = r0; bf[nj2 * 2 + 0][1] = r1;
                bf[nj2 * 2 + 1][0] = r2; bf[nj2 * 2 + 1][1] = r3;
            }
#pragma unroll
            for (int mi = 0; mi < 4; mi++)
#pragma unroll
                for (int nt = 0; nt < 4; nt++)
                    mma_bf16(acc[mi][nt], af[mi], bf[nt][0], bf[nt][1]);
        }
        if (flag) {
#pragma unroll
            for (int s = 6; s < 8; s++) {
                uint32_t af[4][4];
#pragma unroll
                for (int mi = 0; mi < 4; mi++)
                    ldsm_x4(af[mi][0], af[mi][1], af[mi][2], af[mi][3],
                            a_base + (uint32_t)mi * (16 * KPAD * 2) + (uint32_t)s * 32u);
                uint32_t bf[4][2];
#pragma unroll
                for (int nj2 = 0; nj2 < 2; nj2++) {
                    uint32_t r0, r1, r2, r3;
                    ldsm_x4(r0, r1, r2, r3,
                            b_base + (uint32_t)nj2 * (16 * KPAD * 2) + (uint32_t)s * 32u);
                    bf[nj2 * 2 + 0][0] = r0; bf[nj2 * 2 + 0][1] = r1;
                    bf[nj2 * 2 + 1][0] = r2; bf[nj2 * 2 + 1][1] = r3;
                }
#pragma unroll
                for (int mi = 0; mi < 4; mi++)
#pragma unroll
                    for (int nt = 0; nt < 4; nt++)
                        mma_bf16(acc[mi][nt], af[mi], bf[nt][0], bf[nt][1]);
            }
        }

        // --- Epilogue: out = exp2(acc + eb[m] + rc[n]) ---
        const int m0 = mt * TMC;
#pragma unroll
        for (int mi = 0; mi < 4; mi++) {
            int lrow = warp_m + mi * 16 + qrow;
            int row0 = n0 + lrow;
            float rc0 = rc_s[lrow];
            float rc1 = rc_s[lrow + 8];
#pragma unroll
            for (int nt = 0; nt < 4; nt++) {
                int col_l = warp_n + nt * 8 + qcol;
                float2 ebv = *(const float2*)(eb_s + m0 + col_l);
                float* p0 = out + (size_t)row0 * M + m0 + col_l;
                float2 r0, r1;
                r0.x = ex2(acc[mi][nt][0] + ebv.x + rc0);
                r0.y = ex2(acc[mi][nt][1] + ebv.y + rc0);
                r1.x = ex2(acc[mi][nt][2] + ebv.x + rc1);
                r1.y = ex2(acc[mi][nt][3] + ebv.y + rc1);
                *(float2*)(p0) = r0;
                *(float2*)(p0 + (size_t)8 * M) = r1;
            }
        }
        __syncthreads();
    }
}

extern "C" void kernel_launch(void* const* d_in, const int* in_sizes, int n_in,
                              void* d_out, int out_size) {
    const float* x       = (const float*)d_in[0];
    const float* centers = (const float*)d_in[1];
    const float* sigma   = (const float*)d_in[2];
    float* out = (float*)d_out;

    int N = in_sizes[0] / DD;
    int M = in_sizes[1] / DD;

    // reset the adaptivity flag each call (deterministic; async memset is graph-capturable)
    void* flag_ptr = nullptr;
    cudaGetSymbolAddress(&flag_ptr, g_flag);
    cudaMemsetAsync(flag_ptr, 0, sizeof(int));

    rbf_precompute<<<(N * DD) / 256, 256>>>(x, centers, sigma, N, M);

    const int SMEM_BYTES = TNPTS * KPAD * 2 + 2 * TMC * KPAD * 2 + MMAX * 4 + TNPTS * 4; // ~109 KB
    cudaFuncSetAttribute(rbf_gemm, cudaFuncAttributeMaxDynamicSharedMemorySize, SMEM_BYTES);

    rbf_gemm<<<N / TNPTS, 256, SMEM_BYTES>>>(out, N, M);
}

// round 15
// speedup vs baseline: 1.1787x; 1.1173x over previous
#include <cuda_runtime.h>
#include <cuda_bf16.h>
#include <cstdint>

#define DD    32
#define KK    128          // groups: A=(ph,ph,pl,q) * B=(ah,al,ah,w'); group 3 skipped when w'==0
#define KPAD  136          // bf16 per smem row: 272B stride -> ldmatrix conflict-free
#define NROW  16           // int4 chunks per full 128-bf16 row
#define TNPTS 128          // n rows per block
#define TMC   64           // m cols per tile (half-width)
#define HTILE 8            // tiles per block (half of M/TMC)
#define NMAX  16384
#define MMAX  1024

__device__ __nv_bfloat16 g_A[NMAX * KK];
__device__ __nv_bfloat16 g_B[MMAX * KK];
__device__ float g_eb[MMAX];   // CEXP*sum(c^2/s^2) + log2(1/detS)
__device__ float g_rc[NMAX];   // exact fp32: sum_d q_d * wbar_d
__device__ int   g_flag;       // 1 if any w' != 0; pure function of inputs, idempotent

// ---------------- helpers ----------------
__device__ __forceinline__ uint32_t smem_u32(const void* p) {
    uint32_t a;
    asm("{ .reg .u64 t; cvta.to.shared.u64 t, %1; cvt.u32.u64 %0, t; }" : "=r"(a) : "l"(p));
    return a;
}
__device__ __forceinline__ float ex2(float v) {
    float r; asm("ex2.approx.ftz.f32 %0, %1;" : "=f"(r) : "f"(v)); return r;
}
__device__ __forceinline__ void cp16(uint32_t smem_addr, const void* gptr) {
    asm volatile("cp.async.cg.shared.global [%0], [%1], 16;" :: "r"(smem_addr), "l"(gptr));
}
__device__ __forceinline__ void ldsm_x4(uint32_t& r0, uint32_t& r1, uint32_t& r2, uint32_t& r3,
                                        uint32_t addr) {
    asm volatile("ldmatrix.sync.aligned.m8n8.x4.shared.b16 {%0,%1,%2,%3}, [%4];"
                 : "=r"(r0), "=r"(r1), "=r"(r2), "=r"(r3) : "r"(addr));
}
__device__ __forceinline__ void mma_bf16(float* c, const uint32_t* a, uint32_t b0, uint32_t b1) {
    asm volatile(
        "mma.sync.aligned.m16n8k16.row.col.f32.bf16.bf16.f32 "
        "{%0,%1,%2,%3}, {%4,%5,%6,%7}, {%8,%9}, {%0,%1,%2,%3};"
        : "+f"(c[0]), "+f"(c[1]), "+f"(c[2]), "+f"(c[3])
        : "r"(a[0]), "r"(a[1]), "r"(a[2]), "r"(a[3]), "r"(b0), "r"(b1));
}
__device__ __forceinline__ __nv_bfloat16 bfh(float v) { return __float2bfloat16_rn(v); }

// ---------------- fused precompute: one lane per (row, d); warp = one row ----------------
__global__ __launch_bounds__(256) void rbf_precompute(const float* __restrict__ x,
                                                      const float* __restrict__ centers,
                                                      const float* __restrict__ sigma,
                                                      int N, int M) {
    int idx = blockIdx.x * 256 + threadIdx.x;   // idx = row*32 + d
    int d = idx & 31;
    const float CEXP = -0.7213475204444817f;    // -0.5 * log2(e)
    const float LOG2_2PI = 2.6514961294723187f;

    float s0   = sigma[d];                      // reference sigma (center row 0)
    float wbar = CEXP * __frcp_rn(s0 * s0);

    // --- A side: groups [ph, ph, pl, q]; rc = sum q*wbar exact ---
    {
        int n = idx >> 5;
        float v = x[idx];
        __nv_bfloat16 ph = bfh(v);
        __nv_bfloat16 pl = bfh(v - __bfloat162float(ph));
        float q = v * v;
        __nv_bfloat16 qb = bfh(q);
        __nv_bfloat16* row = g_A + (size_t)n * KK + d;
        row[0 * 32] = ph;  row[1 * 32] = ph;  row[2 * 32] = pl;  row[3 * 32] = qb;

        float rc = q * wbar;
#pragma unroll
        for (int o = 16; o > 0; o >>= 1)
            rc += __shfl_xor_sync(0xFFFFFFFFu, rc, o);
        if (d == 0) g_rc[n] = rc;
    }

    // --- B side: groups [ah, al, ah, w'] ---
    if (idx < M * DD) {
        int m = idx >> 5;
        float c  = centers[idx];
        float s  = sigma[idx];
        float s2 = s * s;
        float inv = __frcp_rn(s2);
        float w  = CEXP * inv;
        float wp = w - wbar;                       // residual (0 when sigma uniform)
        float a  = -2.0f * c * w;
        __nv_bfloat16 ah = bfh(a);
        __nv_bfloat16 al = bfh(a - __bfloat162float(ah));
        __nv_bfloat16 wpb = bfh(wp);
        __nv_bfloat16* row = g_B + (size_t)m * KK + d;
        row[0 * 32] = ah;  row[1 * 32] = al;  row[2 * 32] = ah;  row[3 * 32] = wpb;

        // flag: set iff any nonzero residual. Pure function of inputs; never reset
        // (idempotent: same inputs -> same flag on every call).
        unsigned ball = __ballot_sync(0xFFFFFFFFu, wp != 0.0f);
        if (d == 0 && ball) atomicOr(&g_flag, 1);

        float cm = c * c * inv;
        float lg = __log2f(s2);
#pragma unroll
        for (int o = 16; o > 0; o >>= 1) {
            cm += __shfl_xor_sync(0xFFFFFFFFu, cm, o);
            lg += __shfl_xor_sync(0xFFFFFFFFu, lg, o);
        }
        if (d == 0)
            g_eb[m] = fmaf(CEXP, cm, -0.5f * (DD * LOG2_2PI + lg));
    }
}

// ---- n-strip x m-half GEMM: 2 independent blocks/SM, adaptive K, B double-buffered ----
__global__ __launch_bounds__(256, 2)
void rbf_gemm(float* __restrict__ out, int N, int M) {
    extern __shared__ char dyn[];
    __nv_bfloat16* a_s  = (__nv_bfloat16*)dyn;             // [128][KPAD]  34 KB
    __nv_bfloat16* b_s  = a_s + TNPTS * KPAD;              // [2][64][KPAD] 34 KB
    float*         eb_s = (float*)(b_s + 2 * TMC * KPAD);  // [512]          2 KB
    float*         rc_s = eb_s + HTILE * TMC;              // [128]

    const int tid  = threadIdx.x;
    const int wid  = tid >> 5;
    const int lane = tid & 31;
    const int n0     = blockIdx.x * TNPTS;
    const int mhalf0 = blockIdx.y * (HTILE * TMC);          // 0 or 512

    const int flag = g_flag;                    // uniform; 0 => skip group 3 (K=96)
    const int nchunk = flag ? NROW : 12;        // int4 chunks per row actually needed

    const uint32_t a_u = smem_u32(a_s);
    const uint32_t b_u = smem_u32(b_s);
    const uint32_t bufstride = (uint32_t)(TMC * KPAD * 2);

    // --- Prologue: A tile + B tile 0 + eb + rc ---
    for (int i = tid; i < TNPTS * nchunk; i += 256) {
        int r = i / nchunk, c = i - r * nchunk;
        cp16(a_u + (uint32_t)(r * (KPAD * 2) + c * 16),
             (const char*)(g_A + (size_t)(n0 + r) * KK) + c * 16);
    }
    for (int i = tid; i < TMC * nchunk; i += 256) {
        int r = i / nchunk, c = i - r * nchunk;
        cp16(b_u + (uint32_t)(r * (KPAD * 2) + c * 16),
             (const char*)(g_B + (size_t)(mhalf0 + r) * KK) + c * 16);
    }
    asm volatile("cp.async.commit_group;" ::: "memory");
    if (tid < 128) {
        *(float4*)(eb_s + tid * 4) = *(const float4*)(g_eb + mhalf0 + tid * 4);
        rc_s[tid] = g_rc[n0 + tid];
    }
    asm volatile("cp.async.wait_group 0;" ::: "memory");
    __syncthreads();

    // --- Warp tiling: 4 (rows) x 2 (cols) warps; warp tile 32 x 32 ---
    const int warp_m = (wid & 3) * 32;         // n-row offset
    const int warp_n = (wid >> 2) * 32;        // m-col offset

    const uint32_t a_base = a_u + (uint32_t)(warp_m + (lane & 15)) * (KPAD * 2)
                          + ((uint32_t)lane >> 4) * 16u;
    const uint32_t b_frag = (uint32_t)((warp_n + ((lane >> 4) & 1) * 8 + (lane & 7)) * (KPAD * 2))
                          + (uint32_t)((lane >> 3) & 1) * 16u;
    const int qrow = lane >> 2;
    const int qcol = 2 * (lane & 3);

    for (int mt = 0; mt < HTILE; mt++) {
        if (mt + 1 < HTILE) {
            uint32_t dst = b_u + (uint32_t)((mt + 1) & 1) * bufstride;
            const char* src = (const char*)(g_B + (size_t)(mhalf0 + (mt + 1) * TMC) * KK);
            for (int i = tid; i < TMC * nchunk; i += 256) {
                int r = i / nchunk, c = i - r * nchunk;
                cp16(dst + (uint32_t)(r * (KPAD * 2) + c * 16), src + (size_t)r * KK * 2 + c * 16);
            }
            asm volatile("cp.async.commit_group;" ::: "memory");
            asm volatile("cp.async.wait_group 1;" ::: "memory");
        } else {
            asm volatile("cp.async.wait_group 0;" ::: "memory");
        }
        __syncthreads();

        const uint32_t b_base = b_u + (uint32_t)(mt & 1) * bufstride + b_frag;

        float acc[2][4][4];
#pragma unroll
        for (int i = 0; i < 2; i++)
#pragma unroll
            for (int j = 0; j < 4; j++)
#pragma unroll
                for (int k = 0; k < 4; k++) acc[i][j][k] = 0.0f;

        // ksteps 0..5 always; 6..7 (q*w') only if flag
#pragma unroll
        for (int s = 0; s < 6; s++) {
            uint32_t af[2][4];
#pragma unroll
            for (int mi = 0; mi < 2; mi++)
                ldsm_x4(af[mi][0], af[mi][1], af[mi][2], af[mi][3],
                        a_base + (uint32_t)mi * (16 * KPAD * 2) + (uint32_t)s * 32u);
            uint32_t bf[4][2];
#pragma unroll
            for (int nj2 = 0; nj2 < 2; nj2++) {
                uint32_t r0, r1, r2, r3;
                ldsm_x4(r0, r1, r2, r3,
                        b_base + (uint32_t)nj2 * (16 * KPAD * 2) + (uint32_t)s * 32u);
                bf[nj2 * 2 + 0][0] = r0; bf[nj2 * 2 + 0][1] = r1;
                bf[nj2 * 2 + 1][0] = r2; bf[nj2 * 2 + 1][1] = r3;
            }
#pragma unroll
            for (int mi = 0; mi < 2; mi++)
#pragma unroll
                for (int nt = 0; nt < 4; nt++)
                    mma_bf16(acc[mi][nt], af[mi], bf[nt][0], bf[nt][1]);
        }
        if (flag) {
#pragma unroll
            for (int s = 6; s < 8; s++) {
                uint32_t af[2][4];
#pragma unroll
                for (int mi = 0; mi < 2; mi++)
                    ldsm_x4(af[mi][0], af[mi][1], af[mi][2], af[mi][3],
                            a_base + (uint32_t)mi * (16 * KPAD * 2) + (uint32_t)s * 32u);
                uint32_t bf[4][2];
#pragma unroll
                for (int nj2 = 0; nj2 < 2; nj2++) {
                    uint32_t r0, r1, r2, r3;
                    ldsm_x4(r0, r1, r2, r3,
                            b_base + (uint32_t)nj2 * (16 * KPAD * 2) + (uint32_t)s * 32u);
                    bf[nj2 * 2 + 0][0] = r0; bf[nj2 * 2 + 0][1] = r1;
                    bf[nj2 * 2 + 1][0] = r2; bf[nj2 * 2 + 1][1] = r3;
                }
#pragma unroll
                for (int mi = 0; mi < 2; mi++)
#pragma unroll
                    for (int nt = 0; nt < 4; nt++)
                        mma_bf16(acc[mi][nt], af[mi], bf[nt][0], bf[nt][1]);
            }
        }

        // --- Epilogue: out = exp2(acc + eb[m] + rc[n]) ---
        const int m0l = mt * TMC;                    // local to this half
        const int m0g = mhalf0 + m0l;                // global col base
#pragma unroll
        for (int mi = 0; mi < 2; mi++) {
            int lrow = warp_m + mi * 16 + qrow;
            int row0 = n0 + lrow;
            float rc0 = rc_s[lrow];
            float rc1 = rc_s[lrow + 8];
#pragma unroll
            for (int nt = 0; nt < 4; nt++) {
                int col_l = warp_n + nt * 8 + qcol;
                float2 ebv = *(const float2*)(eb_s + m0l + col_l);
                float* p0 = out + (size_t)row0 * M + m0g + col_l;
                float2 r0, r1;
                r0.x = ex2(acc[mi][nt][0] + ebv.x + rc0);
                r0.y = ex2(acc[mi][nt][1] + ebv.y + rc0);
                r1.x = ex2(acc[mi][nt][2] + ebv.x + rc1);
                r1.y = ex2(acc[mi][nt][3] + ebv.y + rc1);
                *(float2*)(p0) = r0;
                *(float2*)(p0 + (size_t)8 * M) = r1;
            }
        }
        __syncthreads();
    }
}

extern "C" void kernel_launch(void* const* d_in, const int* in_sizes, int n_in,
                              void* d_out, int out_size) {
    const float* x       = (const float*)d_in[0];
    const float* centers = (const float*)d_in[1];
    const float* sigma   = (const float*)d_in[2];
    float* out = (float*)d_out;

    int N = in_sizes[0] / DD;
    int M = in_sizes[1] / DD;

    rbf_precompute<<<(N * DD) / 256, 256>>>(x, centers, sigma, N, M);

    const int SMEM_BYTES = TNPTS * KPAD * 2 + 2 * TMC * KPAD * 2
                         + HTILE * TMC * 4 + TNPTS * 4;                 // ~72 KB
    cudaFuncSetAttribute(rbf_gemm, cudaFuncAttributeMaxDynamicSharedMemorySize, SMEM_BYTES);

    dim3 grid(N / TNPTS, 2);
    rbf_gemm<<<grid, 256, SMEM_BYTES>>>(out, N, M);
}